// round 5
// baseline (speedup 1.0000x reference)
#include <cuda_runtime.h>
#include <math.h>

#define LS 48
#define LTm1 47
#define NB 64      // batch
#define E 512
#define H 512
#define VT 32000
#define NROWS 3008      // 47*64 decoder (step,batch) rows
#define NROWS_PAD 3072  // padded to multiple of 128
#define NCHUNK 250      // 32000/128

// ---------------- device scratch (static, allowed) ----------------
__device__ float g_zero[NB * H];
__device__ float g_embs_src[LS * NB * E];
__device__ float g_embs_tgt[LTm1 * NB * E];
__device__ float g_Xf[LS * NB * 2048];
__device__ float g_Xb[LS * NB * 2048];
__device__ float g_Gd[LTm1 * NB * 2048];
__device__ float g_hs[LS * NB * 1024];    // [t][b][1024] fwd||bwd
__device__ float g_hsp[LS * NB * 1024];   // hs_proj [l][b][1024]
__device__ float g_cf[NB * H];
__device__ float g_cb[NB * H];
__device__ float g_cd[NB * H];
__device__ float g_od[NB * H];
__device__ float g_q[NB * 1024];
__device__ float g_ctx[NB * 1024];
__device__ float g_H[NROWS_PAD * H];      // decoder h history (rows m=t*64+b)
__device__ float g_tgt_logit[NROWS];
__device__ float g_maskv[NROWS];
__device__ float g_partial[NROWS_PAD * NCHUNK];
__device__ float g_blk[24];

// grid-barrier state (reset every replay by k_init)
__device__ unsigned g_cnt_e, g_cnt_d;
__device__ volatile unsigned g_sense_e, g_sense_d;

__device__ __forceinline__ float sigm(float x) { return 1.f / (1.f + __expf(-x)); }

__device__ __forceinline__ float f2tf(float x) {
    unsigned u;
    asm("cvt.rna.tf32.f32 %0, %1;" : "=r"(u) : "f"(x));
    return __uint_as_float(u);
}

// fast exp on the FMA pipe
__device__ __forceinline__ float fexp(float x) {
    float y = x * 1.44269504f;
    float fl = floorf(y);
    float f = y - fl;
    float p = fmaf(f, 0.0013333558f, 0.0096181291f);
    p = fmaf(f, p, 0.055504109f);
    p = fmaf(f, p, 0.24022651f);
    p = fmaf(f, p, 0.69314718f);
    p = fmaf(f, p, 1.0f);
    int e = (int)fl;
    return p * __int_as_float((e + 127) << 23);
}

__device__ __forceinline__ void mma_tf32(float* c, unsigned a0, unsigned a1, unsigned a2,
                                         unsigned a3, unsigned b0, unsigned b1) {
    asm volatile(
        "mma.sync.aligned.m16n8k8.row.col.f32.tf32.tf32.f32 "
        "{%0,%1,%2,%3},{%4,%5,%6,%7},{%8,%9},{%0,%1,%2,%3};"
        : "+f"(c[0]), "+f"(c[1]), "+f"(c[2]), "+f"(c[3])
        : "r"(a0), "r"(a1), "r"(a2), "r"(a3), "r"(b0), "r"(b1));
}

// monotonic-sense grid barrier. s = barrier ordinal (1,2,3,...)
__device__ __forceinline__ void gbar(unsigned* cnt, volatile unsigned* sn,
                                     unsigned nb, unsigned s) {
    __syncthreads();
    if (threadIdx.x == 0) {
        __threadfence();
        unsigned a = atomicAdd(cnt, 1u);
        if (a == nb * s - 1u) {
            __threadfence();
            *sn = s;
        } else {
            while (*sn < s) __nanosleep(64);
        }
    }
    __syncthreads();
}

// ---------------- init: zero states + H padding + barrier reset ----------------
__global__ void k_init() {
    int i = blockIdx.x * blockDim.x + threadIdx.x;
    if (i == 0) { g_cnt_e = 0; g_cnt_d = 0; g_sense_e = 0; g_sense_d = 0; }
    int n = NB * H;
    for (int j = i; j < n; j += gridDim.x * blockDim.x) {
        g_zero[j] = 0.f; g_cf[j] = 0.f; g_cb[j] = 0.f;
        g_cd[j] = 0.f; g_od[j] = 0.f;
        g_H[NROWS * H + j] = 0.f;   // pad rows 3008..3071
    }
}

// ---------------- embedding gather ----------------
__global__ void k_gather(const int* __restrict__ tok, const float* __restrict__ emb, int mode) {
    float* out = mode ? g_embs_tgt : g_embs_src;
    int rows = mode ? (LTm1 * NB) : (LS * NB);
    int n4 = rows * (E / 4);
    const float4* e4 = (const float4*)emb;
    float4* o4 = (float4*)out;
    for (int j = blockIdx.x * blockDim.x + threadIdx.x; j < n4; j += gridDim.x * blockDim.x) {
        int r = j >> 7;
        int c = j & 127;
        o4[j] = e4[(size_t)tok[r] * 128 + c];
    }
}

// ---------------- generic 64x64 SGEMM: C = A @ W^T + b1 + b2 ----------------
__global__ void __launch_bounds__(256) k_sgemm64(int mode, const float* __restrict__ W, int ldw,
                                                 const float* __restrict__ b1, const float* __restrict__ b2,
                                                 int K) {
    __shared__ float As[16][64];
    __shared__ float Bs[16][64];
    const float* A; int lda; float* C; int ldc;
    switch (mode) {
        case 0: A = g_embs_src; lda = E;    C = g_Xf;  ldc = 2048; break;
        case 1: A = g_embs_src; lda = E;    C = g_Xb;  ldc = 2048; break;
        case 2: A = g_embs_tgt; lda = E;    C = g_Gd;  ldc = 2048; break;
        default: A = g_hs;      lda = 1024; C = g_hsp; ldc = 1024; break;
    }
    int nb = blockIdx.x, mb = blockIdx.y;
    int tid = threadIdx.x;
    int tx = tid & 15, ty = tid >> 4;
    const float* Ab = A + (size_t)mb * 64 * lda;
    const float* Wb = W + (size_t)nb * 64 * ldw;
    float acc[4][4] = {};
    for (int kb = 0; kb < K; kb += 16) {
#pragma unroll
        for (int i = 0; i < 4; i++) {
            int e = tid + 256 * i;
            int kk = e & 15, r = e >> 4;
            As[kk][r] = Ab[(size_t)r * lda + kb + kk];
            Bs[kk][r] = Wb[(size_t)r * ldw + kb + kk];
        }
        __syncthreads();
#pragma unroll
        for (int kk = 0; kk < 16; kk++) {
            float a[4], w[4];
#pragma unroll
            for (int i = 0; i < 4; i++) a[i] = As[kk][ty * 4 + i];
#pragma unroll
            for (int j = 0; j < 4; j++) w[j] = Bs[kk][tx * 4 + j];
#pragma unroll
            for (int i = 0; i < 4; i++)
#pragma unroll
                for (int j = 0; j < 4; j++) acc[i][j] += a[i] * w[j];
        }
        __syncthreads();
    }
#pragma unroll
    for (int i = 0; i < 4; i++) {
        int r = mb * 64 + ty * 4 + i;
#pragma unroll
        for (int j = 0; j < 4; j++) {
            int n = nb * 64 + tx * 4 + j;
            float v = acc[i][j];
            if (b1) v += b1[n];
            if (b2) v += b2[n];
            C[(size_t)r * ldc + n] = v;
        }
    }
}

// ---------------- persistent encoder: 128 blocks, 48 steps, 1 barrier/step ----------------
__global__ void __launch_bounds__(256) k_enc_persist(const float* __restrict__ Whh_f,
                                                     const float* __restrict__ Whh_b) {
    __shared__ float As[16][64];
    __shared__ float Bs[16][32];
    __shared__ float gbuf[64][33];
    int dir = blockIdx.x >> 6;
    int cu = (blockIdx.x & 63) * 8;
    int tid = threadIdx.x;
    int tx = tid & 15, ty = tid >> 4;
    const float* Whh = dir ? Whh_b : Whh_f;
    unsigned s = 0;

    for (int t = 0; t < LS; t++) {
        const float* hprev; int ldh;
        if (t == 0) { hprev = g_zero; ldh = H; }
        else if (dir == 0) { hprev = g_hs + (size_t)(t - 1) * NB * 1024; ldh = 1024; }
        else { hprev = g_hs + (size_t)(LS - t) * NB * 1024 + 512; ldh = 1024; }

        float acc[4][2] = {};
        for (int kb = 0; kb < H; kb += 16) {
#pragma unroll
            for (int i = 0; i < 4; i++) {
                int e = tid + 256 * i;
                int kk = e & 15, b = e >> 4;
                As[kk][b] = hprev[(size_t)b * ldh + kb + kk];
            }
#pragma unroll
            for (int i = 0; i < 2; i++) {
                int e = tid + 256 * i;
                int kk = e & 15, j = e >> 4;
                int row = ((j >> 3) << 9) + cu + (j & 7);
                Bs[kk][j] = Whh[(size_t)row * H + kb + kk];
            }
            __syncthreads();
#pragma unroll
            for (int kk = 0; kk < 16; kk++) {
                float a0 = As[kk][ty * 4 + 0], a1 = As[kk][ty * 4 + 1];
                float a2 = As[kk][ty * 4 + 2], a3 = As[kk][ty * 4 + 3];
                float w0 = Bs[kk][tx * 2 + 0], w1 = Bs[kk][tx * 2 + 1];
                acc[0][0] += a0 * w0; acc[0][1] += a0 * w1;
                acc[1][0] += a1 * w0; acc[1][1] += a1 * w1;
                acc[2][0] += a2 * w0; acc[2][1] += a2 * w1;
                acc[3][0] += a3 * w0; acc[3][1] += a3 * w1;
            }
            __syncthreads();
        }
#pragma unroll
        for (int i = 0; i < 4; i++)
#pragma unroll
            for (int j = 0; j < 2; j++)
                gbuf[ty * 4 + i][tx * 2 + j] = acc[i][j];
        __syncthreads();
        const float* Xg = dir ? (g_Xb + (size_t)(LS - 1 - t) * NB * 2048)
                              : (g_Xf + (size_t)t * NB * 2048);
        float* cst = dir ? g_cb : g_cf;
        float* hs_out = dir ? (g_hs + (size_t)(LS - 1 - t) * NB * 1024 + 512)
                            : (g_hs + (size_t)t * NB * 1024);
#pragma unroll
        for (int i = 0; i < 2; i++) {
            int cid = tid + 256 * i;
            int b = cid >> 3, cl = cid & 7;
            int cell = cu + cl;
            const float* xb = Xg + (size_t)b * 2048;
            float gi = gbuf[b][cl] + xb[cell];
            float gf = gbuf[b][8 + cl] + xb[512 + cell];
            float gg = gbuf[b][16 + cl] + xb[1024 + cell];
            float go = gbuf[b][24 + cl] + xb[1536 + cell];
            float co = cst[b * H + cell];
            float cn = sigm(gf) * co + sigm(gi) * tanhf(gg);
            float hn = sigm(go) * tanhf(cn);
            cst[b * H + cell] = cn;
            hs_out[(size_t)b * 1024 + cell] = hn;
        }
        if (t < LS - 1) gbar(&g_cnt_e, &g_sense_e, 128u, ++s);
    }
}

// ---------------- persistent decoder: 64 blocks, 47 steps x 4 phases ----------------
union DecShm {
    struct { float As[16][64]; float Bs[16][32]; float gbuf[64][33]; } g;
    struct { float As[32][64]; float Ws[16][33]; } s;
    struct { float sq[1024]; float sv[1024]; float sps[LS]; } a;
};

__global__ void __launch_bounds__(256) k_dec_persist(const float* __restrict__ Wih,
                                                     const float* __restrict__ Whh,
                                                     const float* __restrict__ attn_W,
                                                     const float* __restrict__ attn_v,
                                                     const float* __restrict__ lin_W,
                                                     const float* __restrict__ lin_b) {
    __shared__ DecShm shm;
    int blk = blockIdx.x, tid = threadIdx.x;
    unsigned s = 0;

    for (int t = 0; t < LTm1; t++) {
        // ---- phase 1: gates + LSTM cell (block owns cells cu..cu+7) ----
        {
            int cu = blk * 8;
            int tx = tid & 15, ty = tid >> 4;
            const float* hprev = (t == 0) ? g_zero : (g_H + (size_t)(t - 1) * NB * H);
            float acc[4][2] = {};
            for (int part = 0; part < 2; part++) {
                const float* Ain = (part == 0) ? g_od : hprev;
                bool cg = (part == 0);   // g_od address-reused across steps -> L2 loads
                for (int kb = 0; kb < H; kb += 16) {
#pragma unroll
                    for (int i = 0; i < 4; i++) {
                        int e = tid + 256 * i;
                        int kk = e & 15, b = e >> 4;
                        const float* p = &Ain[(size_t)b * H + kb + kk];
                        shm.g.As[kk][b] = cg ? __ldcg(p) : *p;
                    }
#pragma unroll
                    for (int i = 0; i < 2; i++) {
                        int e = tid + 256 * i;
                        int kk = e & 15, j = e >> 4;
                        int row = ((j >> 3) << 9) + cu + (j & 7);
                        shm.g.Bs[kk][j] = (part == 0) ? Wih[(size_t)row * 1024 + 512 + kb + kk]
                                                      : Whh[(size_t)row * H + kb + kk];
                    }
                    __syncthreads();
#pragma unroll
                    for (int kk = 0; kk < 16; kk++) {
                        float a0 = shm.g.As[kk][ty * 4 + 0], a1 = shm.g.As[kk][ty * 4 + 1];
                        float a2 = shm.g.As[kk][ty * 4 + 2], a3 = shm.g.As[kk][ty * 4 + 3];
                        float w0 = shm.g.Bs[kk][tx * 2 + 0], w1 = shm.g.Bs[kk][tx * 2 + 1];
                        acc[0][0] += a0 * w0; acc[0][1] += a0 * w1;
                        acc[1][0] += a1 * w0; acc[1][1] += a1 * w1;
                        acc[2][0] += a2 * w0; acc[2][1] += a2 * w1;
                        acc[3][0] += a3 * w0; acc[3][1] += a3 * w1;
                    }
                    __syncthreads();
                }
            }
#pragma unroll
            for (int i = 0; i < 4; i++)
#pragma unroll
                for (int j = 0; j < 2; j++)
                    shm.g.gbuf[ty * 4 + i][tx * 2 + j] = acc[i][j];
            __syncthreads();
            const float* Xg = g_Gd + (size_t)t * NB * 2048;
#pragma unroll
            for (int i = 0; i < 2; i++) {
                int cid = tid + 256 * i;
                int b = cid >> 3, cl = cid & 7;
                int cell = cu + cl;
                const float* xb = Xg + (size_t)b * 2048;
                float gi = shm.g.gbuf[b][cl] + xb[cell];
                float gf = shm.g.gbuf[b][8 + cl] + xb[512 + cell];
                float gg = shm.g.gbuf[b][16 + cl] + xb[1024 + cell];
                float go = shm.g.gbuf[b][24 + cl] + xb[1536 + cell];
                float co = g_cd[b * H + cell];
                float cn = sigm(gf) * co + sigm(gi) * tanhf(gg);
                float hn = sigm(go) * tanhf(cn);
                g_cd[b * H + cell] = cn;
                g_H[((size_t)t * NB + b) * H + cell] = hn;
            }
        }
        gbar(&g_cnt_d, &g_sense_d, 64u, ++s);

        // ---- phase 2: q = h @ Wq^T (block owns 16 q-cols) ----
        {
            const float* A1 = g_H + (size_t)t * NB * H;
            int tn = tid & 15, tb = tid >> 4;
            int n0 = blk * 16;
            float acc[4] = {};
            for (int k0 = 0; k0 < H; k0 += 32) {
#pragma unroll
                for (int i = 0; i < 8; i++) {
                    int e = tid + 256 * i;
                    int kk = e & 31, b = e >> 5;
                    shm.s.As[kk][b] = A1[(size_t)b * H + k0 + kk];
                }
#pragma unroll
                for (int i = 0; i < 2; i++) {
                    int e = tid + 256 * i;
                    int kk = e & 31, j = e >> 5;
                    shm.s.Ws[j][kk] = attn_W[(size_t)(n0 + j) * 1536 + k0 + kk];
                }
                __syncthreads();
#pragma unroll
                for (int kk = 0; kk < 32; kk++) {
                    float w = shm.s.Ws[tn][kk];
#pragma unroll
                    for (int i = 0; i < 4; i++) acc[i] += shm.s.As[kk][tb * 4 + i] * w;
                }
                __syncthreads();
            }
            int n = n0 + tn;
#pragma unroll
            for (int i = 0; i < 4; i++)
                g_q[(size_t)(tb * 4 + i) * 1024 + n] = acc[i];
        }
        gbar(&g_cnt_d, &g_sense_d, 64u, ++s);

        // ---- phase 3: attention (block = batch) ----
        {
            int b = blk;
#pragma unroll
            for (int i = 0; i < 4; i++) {
                int k = tid + 256 * i;
                shm.a.sq[k] = __ldcg(&g_q[b * 1024 + k]);
                shm.a.sv[k] = attn_v[k];
            }
            __syncthreads();
            int wid = tid >> 5, lane = tid & 31;
            for (int l = wid; l < LS; l += 8) {
                const float* hp = g_hsp + ((size_t)l * NB + b) * 1024;
                float sc = 0.f;
                for (int k = lane; k < 1024; k += 32) sc += shm.a.sv[k] * tanhf(hp[k] + shm.a.sq[k]);
#pragma unroll
                for (int o = 16; o; o >>= 1) sc += __shfl_down_sync(0xffffffff, sc, o);
                if (lane == 0) shm.a.sps[l] = sc;
            }
            __syncthreads();
            if (tid == 0) {
                float mx = -1e30f;
                for (int l = 0; l < LS; l++) mx = fmaxf(mx, shm.a.sps[l]);
                float sm = 0.f;
                for (int l = 0; l < LS; l++) { float e = __expf(shm.a.sps[l] - mx); shm.a.sps[l] = e; sm += e; }
                float inv = 1.f / sm;
                for (int l = 0; l < LS; l++) shm.a.sps[l] *= inv;
            }
            __syncthreads();
#pragma unroll
            for (int i = 0; i < 4; i++) {
                int k = tid + 256 * i;
                float acc = 0.f;
                for (int l = 0; l < LS; l++) acc += shm.a.sps[l] * g_hs[((size_t)l * NB + b) * 1024 + k];
                g_ctx[b * 1024 + k] = acc;
            }
        }
        gbar(&g_cnt_d, &g_sense_d, 64u, ++s);

        // ---- phase 4: o = tanh([ctx,h] @ lin_W^T + b) (block owns 8 o-cols) ----
        {
            const float* A2 = g_H + (size_t)t * NB * H;
            int tn = tid & 7, tb = tid >> 3;     // tb 0..31, 2 batches each
            int n0 = blk * 8;
            float acc[2] = {};
            for (int k0 = 0; k0 < 1536; k0 += 32) {
                const float* src; int lda; int col; bool cg;
                if (k0 < 1024) { src = g_ctx; lda = 1024; col = k0; cg = true; }
                else { src = A2; lda = H; col = k0 - 1024; cg = false; }
#pragma unroll
                for (int i = 0; i < 8; i++) {
                    int e = tid + 256 * i;
                    int kk = e & 31, b = e >> 5;
                    const float* p = &src[(size_t)b * lda + col + kk];
                    shm.s.As[kk][b] = cg ? __ldcg(p) : *p;
                }
                {
                    int kk = tid & 31, j = tid >> 5;   // 8 rows x 32 k
                    shm.s.Ws[j][kk] = lin_W[(size_t)(n0 + j) * 1536 + k0 + kk];
                }
                __syncthreads();
#pragma unroll
                for (int kk = 0; kk < 32; kk++) {
                    float w = shm.s.Ws[tn][kk];
#pragma unroll
                    for (int i = 0; i < 2; i++) acc[i] += shm.s.As[kk][tb * 2 + i] * w;
                }
                __syncthreads();
            }
            int n = n0 + tn;
            float bv = lin_b[n];
#pragma unroll
            for (int i = 0; i < 2; i++)
                g_od[(size_t)(tb * 2 + i) * H + n] = tanhf(acc[i] + bv);
        }
        if (t < LTm1 - 1) gbar(&g_cnt_d, &g_sense_d, 64u, ++s);
    }
}

// ---------------- target logits (one warp per row) ----------------
__global__ void k_tgt(const int* __restrict__ ts, const float* __restrict__ oW,
                      const float* __restrict__ ob) {
    int gw = blockIdx.x * 8 + (threadIdx.x >> 5);
    int lane = threadIdx.x & 31;
    if (gw >= NROWS) return;
    int tok = ts[gw + NB];
    const float* h = g_H + (size_t)gw * H;
    const float* w = oW + (size_t)tok * H;
    float s = 0.f;
    for (int k = lane; k < H; k += 32) s += h[k] * w[k];
#pragma unroll
    for (int o = 16; o; o >>= 1) s += __shfl_down_sync(0xffffffff, s, o);
    if (lane == 0) {
        g_tgt_logit[gw] = s + ob[tok];
        g_maskv[gw] = (tok != 0) ? 1.f : 0.f;
    }
}

// ---------------- tf32 tensor-core GEMM + fused exp row-sums ----------------
__global__ void __launch_bounds__(256) k_lse(const float* __restrict__ oW,
                                             const float* __restrict__ ob) {
    __shared__ float As[16][132];
    __shared__ float Bs[16][132];
    __shared__ float red[128][8];
    int nb = blockIdx.x, mb = blockIdx.y;
    int tid = threadIdx.x;
    int lane = tid & 31, wid = tid >> 5;
    int wm = wid & 3, wn = wid >> 2;
    int mo = wm * 32, no = wn * 64;

    const float* Ab = g_H + (size_t)mb * 128 * H;
    const float* Wb = oW + (size_t)nb * 128 * H;

    int r0 = tid >> 2, q0 = tid & 3;
    int r1 = (tid + 256) >> 2, q1 = (tid + 256) & 3;

    float c[2][8][4];
#pragma unroll
    for (int mt = 0; mt < 2; mt++)
#pragma unroll
        for (int nt = 0; nt < 8; nt++)
#pragma unroll
            for (int j = 0; j < 4; j++) c[mt][nt][j] = 0.f;

    float4 pa0 = *(const float4*)&Ab[(size_t)r0 * H + q0 * 4];
    float4 pa1 = *(const float4*)&Ab[(size_t)r1 * H + q1 * 4];
    float4 pb0 = *(const float4*)&Wb[(size_t)r0 * H + q0 * 4];
    float4 pb1 = *(const float4*)&Wb[(size_t)r1 * H + q1 * 4];

    for (int kb = 0; kb < H; kb += 16) {
        As[q0 * 4 + 0][r0] = f2tf(pa0.x); As[q0 * 4 + 1][r0] = f2tf(pa0.y);
        As[q0 * 4 + 2][r0] = f2tf(pa0.z); As[q0 * 4 + 3][r0] = f2tf(pa0.w);
        As[q1 * 4 + 0][r1] = f2tf(pa1.x); As[q1 * 4 + 1][r1] = f2tf(pa1.y);
        As[q1 * 4 + 2][r1] = f2tf(pa1.z); As[q1 * 4 + 3][r1] = f2tf(pa1.w);
        Bs[q0 * 4 + 0][r0] = f2tf(pb0.x); Bs[q0 * 4 + 1][r0] = f2tf(pb0.y);
        Bs[q0 * 4 + 2][r0] = f2tf(pb0.z); Bs[q0 * 4 + 3][r0] = f2tf(pb0.w);
        Bs[q1 * 4 + 0][r1] = f2tf(pb1.x); Bs[q1 * 4 + 1][r1] = f2tf(pb1.y);
        Bs[q1 * 4 + 2][r1] = f2tf(pb1.z); Bs[q1 * 4 + 3][r1] = f2tf(pb1.w);
        __syncthreads();

        int kn = kb + 16;
        if (kn < H) {
            pa0 = *(const float4*)&Ab[(size_t)r0 * H + kn + q0 * 4];
            pa1 = *(const float4*)&Ab[(size_t)r1 * H + kn + q1 * 4];
            pb0 = *(const float4*)&Wb[(size_t)r0 * H + kn + q0 * 4];
            pb1 = *(const float4*)&Wb[(size_t)r1 * H + kn + q1 * 4];
        }

#pragma unroll
        for (int ks = 0; ks < 16; ks += 8) {
            unsigned a[2][4];
#pragma unroll
            for (int mt = 0; mt < 2; mt++) {
                int mc = mo + mt * 16 + (lane >> 2);
                a[mt][0] = __float_as_uint(As[ks + (lane & 3)][mc]);
                a[mt][1] = __float_as_uint(As[ks + (lane & 3)][mc + 8]);
                a[mt][2] = __float_as_uint(As[ks + 4 + (lane & 3)][mc]);
                a[mt][3] = __float_as_uint(As[ks + 4 + (lane & 3)][mc + 8]);
            }
#pragma unroll
            for (int nt = 0; nt < 8; nt++) {
                int nc = no + nt * 8 + (lane >> 2);
                unsigned b0 = __float_as_uint(Bs[ks + (lane & 3)][nc]);
                unsigned b1 = __float_as_uint(Bs[ks + 4 + (lane & 3)][nc]);
                mma_tf32(c[0][nt], a[0][0], a[0][1], a[0][2], a[0][3], b0, b1);
                mma_tf32(c[1][nt], a[1][0], a[1][1], a[1][2], a[1][3], b0, b1);
            }
        }
        __syncthreads();
    }

    float bv0[8], bv1[8];
#pragma unroll
    for (int nt = 0; nt < 8; nt++) {
        int n = nb * 128 + no + nt * 8 + 2 * (lane & 3);
        bv0[nt] = ob[n];
        bv1[nt] = ob[n + 1];
    }

#pragma unroll
    for (int mt = 0; mt < 2; mt++) {
        float slo = 0.f, shi = 0.f;
#pragma unroll
        for (int nt = 0; nt < 8; nt++) {
            slo += fexp(c[mt][nt][0] + bv0[nt]) + fexp(c[mt][nt][1] + bv1[nt]);
            shi += fexp(c[mt][nt][2] + bv0[nt]) + fexp(c[mt][nt][3] + bv1[nt]);
        }
        int rlo = mo + mt * 16 + (lane >> 2);
        red[rlo][wn * 4 + (lane & 3)] = slo;
        red[rlo + 8][wn * 4 + (lane & 3)] = shi;
    }
    __syncthreads();
    if (tid < 128) {
        float s = 0.f;
#pragma unroll
        for (int x = 0; x < 8; x++) s += red[tid][x];
        g_partial[((size_t)mb * 128 + tid) * NCHUNK + nb] = s;
    }
}

// ---------------- final reductions ----------------
__global__ void k_red1() {
    __shared__ float s1[256], s2[256];
    int m = blockIdx.x * 256 + threadIdx.x;
    float v = 0.f, mk = 0.f;
    if (m < NROWS) {
        float s = 0.f;
        const float* p = g_partial + (size_t)m * NCHUNK;
        for (int c = 0; c < NCHUNK; c++) s += p[c];
        mk = g_maskv[m];
        v = (logf(s) - g_tgt_logit[m]) * mk;
    }
    s1[threadIdx.x] = v; s2[threadIdx.x] = mk;
    __syncthreads();
    for (int o = 128; o; o >>= 1) {
        if (threadIdx.x < o) { s1[threadIdx.x] += s1[threadIdx.x + o]; s2[threadIdx.x] += s2[threadIdx.x + o]; }
        __syncthreads();
    }
    if (threadIdx.x == 0) { g_blk[blockIdx.x * 2] = s1[0]; g_blk[blockIdx.x * 2 + 1] = s2[0]; }
}

__global__ void k_red2(float* out) {
    if (threadIdx.x == 0) {
        float a = 0.f, b = 0.f;
        for (int i = 0; i < 12; i++) { a += g_blk[i * 2]; b += g_blk[i * 2 + 1]; }
        out[0] = a / b;
    }
}

// ---------------- launcher ----------------
extern "C" void kernel_launch(void* const* d_in, const int* in_sizes, int n_in,
                              void* d_out, int out_size) {
    const int* xs = (const int*)d_in[0];
    const int* ts = (const int*)d_in[1];
    const float* src_emb = (const float*)d_in[2];
    const float* tgt_emb = (const float*)d_in[3];
    const float* encf_Wih = (const float*)d_in[4];
    const float* encf_Whh = (const float*)d_in[5];
    const float* encf_bih = (const float*)d_in[6];
    const float* encf_bhh = (const float*)d_in[7];
    const float* encb_Wih = (const float*)d_in[8];
    const float* encb_Whh = (const float*)d_in[9];
    const float* encb_bih = (const float*)d_in[10];
    const float* encb_bhh = (const float*)d_in[11];
    const float* dec_Wih = (const float*)d_in[12];
    const float* dec_Whh = (const float*)d_in[13];
    const float* dec_bih = (const float*)d_in[14];
    const float* dec_bhh = (const float*)d_in[15];
    const float* attn_W = (const float*)d_in[16];
    const float* attn_v = (const float*)d_in[17];
    const float* lin_W = (const float*)d_in[18];
    const float* lin_b = (const float*)d_in[19];
    const float* out_W = (const float*)d_in[20];
    const float* out_b = (const float*)d_in[21];

    k_init<<<64, 256>>>();
    k_gather<<<1024, 256>>>(xs, src_emb, 0);
    k_gather<<<1024, 256>>>(ts, tgt_emb, 1);

    // input-gate precompute GEMMs
    k_sgemm64<<<dim3(32, 48), 256>>>(0, encf_Wih, 512, encf_bih, encf_bhh, 512);
    k_sgemm64<<<dim3(32, 48), 256>>>(1, encb_Wih, 512, encb_bih, encb_bhh, 512);
    k_sgemm64<<<dim3(32, 47), 256>>>(2, dec_Wih, 1024, dec_bih, dec_bhh, 512);

    // persistent encoder (both directions, 48 steps, internal grid barriers)
    k_enc_persist<<<128, 256>>>(encf_Whh, encb_Whh);

    // hs_proj = hs @ Wk^T   (Wk = attn_W[:, 512:], ld 1536)
    k_sgemm64<<<dim3(16, 48), 256>>>(3, attn_W + 512, 1536, nullptr, nullptr, 1024);

    // persistent decoder (47 steps x 4 phases, internal grid barriers)
    k_dec_persist<<<64, 256>>>(dec_Wih, dec_Whh, attn_W, attn_v, lin_W, lin_b);

    // output projection + NLL
    k_tgt<<<376, 256>>>(ts, out_W, out_b);
    k_lse<<<dim3(NCHUNK, NROWS_PAD / 128), 256>>>(out_W, out_b);
    k_red1<<<12, 256>>>();
    k_red2<<<1, 32>>>((float*)d_out);
}

// round 6
// speedup vs baseline: 1.7661x; 1.7661x over previous
#include <cuda_runtime.h>
#include <math.h>

#define LS 48
#define LTm1 47
#define NB 64      // batch
#define E 512
#define H 512
#define VT 32000
#define NROWS 3008      // 47*64 decoder (step,batch) rows
#define NROWS_PAD 3072  // padded to multiple of 128
#define NCHUNK 250      // 32000/128

// ---------------- device scratch (static, allowed) ----------------
__device__ float g_zero[NB * H];
__device__ float g_embs_src[LS * NB * E];
__device__ float g_embs_tgt[NROWS_PAD * E];     // padded to 3072 rows
__device__ float g_Xf[LS * NB * 2048];
__device__ float g_Xb[LS * NB * 2048];
__device__ float g_Gd[NROWS_PAD * 2048];        // padded to 3072 rows
__device__ float g_hs[LS * NB * 1024];    // [t][b][1024] fwd||bwd
__device__ float g_hsp[LS * NB * 1024];   // hs_proj [l][b][1024]
__device__ float g_cf[NB * H];
__device__ float g_cb[NB * H];
__device__ float g_cd[NB * H];
__device__ float g_od[NB * H];
__device__ float g_q[NB * 1024];
__device__ float g_ctx[NB * 1024];
__device__ float g_H[NROWS_PAD * H];      // decoder h history (rows m=t*64+b)
__device__ float g_tgt_logit[NROWS];
__device__ float g_maskv[NROWS];
__device__ float g_partial[NROWS_PAD * NCHUNK];
__device__ float g_blk[24];

__device__ __forceinline__ float sigm(float x) { return 1.f / (1.f + __expf(-x)); }

__device__ __forceinline__ float f2tf(float x) {
    unsigned u;
    asm("cvt.rna.tf32.f32 %0, %1;" : "=r"(u) : "f"(x));
    return __uint_as_float(u);
}

// fast exp on the FMA pipe
__device__ __forceinline__ float fexp(float x) {
    float y = x * 1.44269504f;
    float fl = floorf(y);
    float f = y - fl;
    float p = fmaf(f, 0.0013333558f, 0.0096181291f);
    p = fmaf(f, p, 0.055504109f);
    p = fmaf(f, p, 0.24022651f);
    p = fmaf(f, p, 0.69314718f);
    p = fmaf(f, p, 1.0f);
    int e = (int)fl;
    return p * __int_as_float((e + 127) << 23);
}

__device__ __forceinline__ void mma_tf32(float* c, unsigned a0, unsigned a1, unsigned a2,
                                         unsigned a3, unsigned b0, unsigned b1) {
    asm volatile(
        "mma.sync.aligned.m16n8k8.row.col.f32.tf32.tf32.f32 "
        "{%0,%1,%2,%3},{%4,%5,%6,%7},{%8,%9},{%0,%1,%2,%3};"
        : "+f"(c[0]), "+f"(c[1]), "+f"(c[2]), "+f"(c[3])
        : "r"(a0), "r"(a1), "r"(a2), "r"(a3), "r"(b0), "r"(b1));
}

// ---------------- init: zero states + paddings ----------------
__global__ void k_init() {
    int i = blockIdx.x * blockDim.x + threadIdx.x;
    int n = NB * H;   // 32768
    for (int j = i; j < n; j += gridDim.x * blockDim.x) {
        g_zero[j] = 0.f; g_cf[j] = 0.f; g_cb[j] = 0.f;
        g_cd[j] = 0.f; g_od[j] = 0.f;
        g_H[NROWS * H + j] = 0.f;           // pad rows 3008..3071 (NB*H elems)
        g_embs_tgt[NROWS * E + j] = 0.f;    // pad rows 3008..3071 (64*512 elems)
    }
}

// ---------------- embedding gather ----------------
__global__ void k_gather(const int* __restrict__ tok, const float* __restrict__ emb, int mode) {
    float* out = mode ? g_embs_tgt : g_embs_src;
    int rows = mode ? (LTm1 * NB) : (LS * NB);
    int n4 = rows * (E / 4);
    const float4* e4 = (const float4*)emb;
    float4* o4 = (float4*)out;
    for (int j = blockIdx.x * blockDim.x + threadIdx.x; j < n4; j += gridDim.x * blockDim.x) {
        int r = j >> 7;
        int c = j & 127;
        o4[j] = e4[(size_t)tok[r] * 128 + c];
    }
}

// ---------------- big fp32 GEMM: C = A @ W^T + b1 + b2, tile 128x128x16, 8x8 micro ----------------
// modes: 0: embs_src->Xf, 1: embs_src->Xb, 2: embs_tgt->Gd, 3: hs->hsp
__global__ void __launch_bounds__(256) k_bgemm(int mode, const float* __restrict__ W, int ldw,
                                               const float* __restrict__ b1, const float* __restrict__ b2,
                                               int K) {
    __shared__ float As[16][132];
    __shared__ float Bs[16][132];
    const float* A; int lda; float* C; int ldc;
    switch (mode) {
        case 0: A = g_embs_src; lda = E;    C = g_Xf;  ldc = 2048; break;
        case 1: A = g_embs_src; lda = E;    C = g_Xb;  ldc = 2048; break;
        case 2: A = g_embs_tgt; lda = E;    C = g_Gd;  ldc = 2048; break;
        default: A = g_hs;      lda = 1024; C = g_hsp; ldc = 1024; break;
    }
    int nb = blockIdx.x, mb = blockIdx.y;
    int tid = threadIdx.x;
    int tx = tid & 15, ty = tid >> 4;

    const float* Ab = A + (size_t)mb * 128 * lda;
    const float* Wb = W + (size_t)nb * 128 * ldw;

    int r0 = tid >> 2, q0 = tid & 3;
    int r1 = (tid + 256) >> 2, q1 = (tid + 256) & 3;

    float acc[8][8];
#pragma unroll
    for (int i = 0; i < 8; i++)
#pragma unroll
        for (int j = 0; j < 8; j++) acc[i][j] = 0.f;

    float4 pa0 = *(const float4*)&Ab[(size_t)r0 * lda + q0 * 4];
    float4 pa1 = *(const float4*)&Ab[(size_t)r1 * lda + q1 * 4];
    float4 pb0 = *(const float4*)&Wb[(size_t)r0 * ldw + q0 * 4];
    float4 pb1 = *(const float4*)&Wb[(size_t)r1 * ldw + q1 * 4];

    for (int kb = 0; kb < K; kb += 16) {
        As[q0 * 4 + 0][r0] = pa0.x; As[q0 * 4 + 1][r0] = pa0.y;
        As[q0 * 4 + 2][r0] = pa0.z; As[q0 * 4 + 3][r0] = pa0.w;
        As[q1 * 4 + 0][r1] = pa1.x; As[q1 * 4 + 1][r1] = pa1.y;
        As[q1 * 4 + 2][r1] = pa1.z; As[q1 * 4 + 3][r1] = pa1.w;
        Bs[q0 * 4 + 0][r0] = pb0.x; Bs[q0 * 4 + 1][r0] = pb0.y;
        Bs[q0 * 4 + 2][r0] = pb0.z; Bs[q0 * 4 + 3][r0] = pb0.w;
        Bs[q1 * 4 + 0][r1] = pb1.x; Bs[q1 * 4 + 1][r1] = pb1.y;
        Bs[q1 * 4 + 2][r1] = pb1.z; Bs[q1 * 4 + 3][r1] = pb1.w;
        __syncthreads();

        int kn = kb + 16;
        if (kn < K) {
            pa0 = *(const float4*)&Ab[(size_t)r0 * lda + kn + q0 * 4];
            pa1 = *(const float4*)&Ab[(size_t)r1 * lda + kn + q1 * 4];
            pb0 = *(const float4*)&Wb[(size_t)r0 * ldw + kn + q0 * 4];
            pb1 = *(const float4*)&Wb[(size_t)r1 * ldw + kn + q1 * 4];
        }

#pragma unroll
        for (int kk = 0; kk < 16; kk++) {
            float4 a0 = *(const float4*)&As[kk][ty * 8];
            float4 a1 = *(const float4*)&As[kk][ty * 8 + 4];
            float4 w0 = *(const float4*)&Bs[kk][tx * 8];
            float4 w1 = *(const float4*)&Bs[kk][tx * 8 + 4];
            float av[8] = {a0.x, a0.y, a0.z, a0.w, a1.x, a1.y, a1.z, a1.w};
            float wv[8] = {w0.x, w0.y, w0.z, w0.w, w1.x, w1.y, w1.z, w1.w};
#pragma unroll
            for (int i = 0; i < 8; i++)
#pragma unroll
                for (int j = 0; j < 8; j++) acc[i][j] = fmaf(av[i], wv[j], acc[i][j]);
        }
        __syncthreads();
    }

    float bias[8];
#pragma unroll
    for (int j = 0; j < 8; j++) {
        int n = nb * 128 + tx * 8 + j;
        float v = 0.f;
        if (b1) v += b1[n];
        if (b2) v += b2[n];
        bias[j] = v;
    }
#pragma unroll
    for (int i = 0; i < 8; i++) {
        int r = mb * 128 + ty * 8 + i;
#pragma unroll
        for (int j = 0; j < 8; j++) {
            int n = nb * 128 + tx * 8 + j;
            C[(size_t)r * ldc + n] = acc[i][j] + bias[j];
        }
    }
}

// ---------------- encoder step (both directions), register-prefetched ----------------
__global__ void __launch_bounds__(256) k_enc_step(int t, const float* __restrict__ Whh_f,
                                                  const float* __restrict__ Whh_b) {
    __shared__ float As[16][64];
    __shared__ float Bs[16][32];
    __shared__ float gbuf[64][33];
    int dir = blockIdx.y;
    int cu = blockIdx.x * 8;
    int tid = threadIdx.x;
    const float* Whh = dir ? Whh_b : Whh_f;
    const float* hprev; int ldh;
    if (t == 0) { hprev = g_zero; ldh = H; }
    else if (dir == 0) { hprev = g_hs + (size_t)(t - 1) * NB * 1024; ldh = 1024; }
    else { hprev = g_hs + (size_t)(LS - t) * NB * 1024 + 512; ldh = 1024; }
    int tx = tid & 15, ty = tid >> 4;

    float pa[4], pb[2];
#pragma unroll
    for (int i = 0; i < 4; i++) {
        int e = tid + 256 * i;
        pa[i] = hprev[(size_t)(e >> 4) * ldh + (e & 15)];
    }
#pragma unroll
    for (int i = 0; i < 2; i++) {
        int e = tid + 256 * i;
        int j = e >> 4;
        int row = ((j >> 3) << 9) + cu + (j & 7);
        pb[i] = Whh[(size_t)row * H + (e & 15)];
    }

    float acc[4][2] = {};
    for (int kb = 0; kb < H; kb += 16) {
#pragma unroll
        for (int i = 0; i < 4; i++) {
            int e = tid + 256 * i;
            As[e & 15][e >> 4] = pa[i];
        }
#pragma unroll
        for (int i = 0; i < 2; i++) {
            int e = tid + 256 * i;
            Bs[e & 15][e >> 4] = pb[i];
        }
        __syncthreads();
        int kn = kb + 16;
        if (kn < H) {
#pragma unroll
            for (int i = 0; i < 4; i++) {
                int e = tid + 256 * i;
                pa[i] = hprev[(size_t)(e >> 4) * ldh + kn + (e & 15)];
            }
#pragma unroll
            for (int i = 0; i < 2; i++) {
                int e = tid + 256 * i;
                int j = e >> 4;
                int row = ((j >> 3) << 9) + cu + (j & 7);
                pb[i] = Whh[(size_t)row * H + kn + (e & 15)];
            }
        }
#pragma unroll
        for (int kk = 0; kk < 16; kk++) {
            float a0 = As[kk][ty * 4 + 0], a1 = As[kk][ty * 4 + 1];
            float a2 = As[kk][ty * 4 + 2], a3 = As[kk][ty * 4 + 3];
            float w0 = Bs[kk][tx * 2 + 0], w1 = Bs[kk][tx * 2 + 1];
            acc[0][0] += a0 * w0; acc[0][1] += a0 * w1;
            acc[1][0] += a1 * w0; acc[1][1] += a1 * w1;
            acc[2][0] += a2 * w0; acc[2][1] += a2 * w1;
            acc[3][0] += a3 * w0; acc[3][1] += a3 * w1;
        }
        __syncthreads();
    }
#pragma unroll
    for (int i = 0; i < 4; i++)
#pragma unroll
        for (int j = 0; j < 2; j++)
            gbuf[ty * 4 + i][tx * 2 + j] = acc[i][j];
    __syncthreads();
    const float* Xg = dir ? (g_Xb + (size_t)(LS - 1 - t) * NB * 2048)
                          : (g_Xf + (size_t)t * NB * 2048);
    float* cst = dir ? g_cb : g_cf;
    float* hs_out = dir ? (g_hs + (size_t)(LS - 1 - t) * NB * 1024 + 512)
                        : (g_hs + (size_t)t * NB * 1024);
#pragma unroll
    for (int i = 0; i < 2; i++) {
        int cid = tid + 256 * i;
        int b = cid >> 3, cl = cid & 7;
        int cell = cu + cl;
        const float* xb = Xg + (size_t)b * 2048;
        float gi = gbuf[b][cl] + xb[cell];
        float gf = gbuf[b][8 + cl] + xb[512 + cell];
        float gg = gbuf[b][16 + cl] + xb[1024 + cell];
        float go = gbuf[b][24 + cl] + xb[1536 + cell];
        float co = cst[b * H + cell];
        float cn = sigm(gf) * co + sigm(gi) * tanhf(gg);
        float hn = sigm(go) * tanhf(cn);
        cst[b * H + cell] = cn;
        hs_out[(size_t)b * 1024 + cell] = hn;
    }
}

// ---------------- decoder gates, register-prefetched ----------------
__global__ void __launch_bounds__(256) k_dec_gates(int t, const float* __restrict__ Wih,
                                                   const float* __restrict__ Whh) {
    __shared__ float As[16][64];
    __shared__ float Bs[16][32];
    __shared__ float gbuf[64][33];
    int cu = blockIdx.x * 8;
    int tid = threadIdx.x;
    int tx = tid & 15, ty = tid >> 4;
    const float* hprev = (t == 0) ? g_zero : (g_H + (size_t)(t - 1) * NB * H);

    float pa[4], pb[2];
    // prefetch idx 0: part 0 (A=g_od, W=Wih[:,512:]), kb=0
#pragma unroll
    for (int i = 0; i < 4; i++) {
        int e = tid + 256 * i;
        pa[i] = g_od[(size_t)(e >> 4) * H + (e & 15)];
    }
#pragma unroll
    for (int i = 0; i < 2; i++) {
        int e = tid + 256 * i;
        int j = e >> 4;
        int row = ((j >> 3) << 9) + cu + (j & 7);
        pb[i] = Wih[(size_t)row * 1024 + 512 + (e & 15)];
    }

    float acc[4][2] = {};
    for (int idx = 0; idx < 64; idx++) {
#pragma unroll
        for (int i = 0; i < 4; i++) {
            int e = tid + 256 * i;
            As[e & 15][e >> 4] = pa[i];
        }
#pragma unroll
        for (int i = 0; i < 2; i++) {
            int e = tid + 256 * i;
            Bs[e & 15][e >> 4] = pb[i];
        }
        __syncthreads();
        int nx = idx + 1;
        if (nx < 64) {
            int part = nx >> 5;
            int kb = (nx & 31) * 16;
            const float* Ain = part ? hprev : g_od;
#pragma unroll
            for (int i = 0; i < 4; i++) {
                int e = tid + 256 * i;
                pa[i] = Ain[(size_t)(e >> 4) * H + kb + (e & 15)];
            }
#pragma unroll
            for (int i = 0; i < 2; i++) {
                int e = tid + 256 * i;
                int j = e >> 4;
                int row = ((j >> 3) << 9) + cu + (j & 7);
                pb[i] = part ? Whh[(size_t)row * H + kb + (e & 15)]
                             : Wih[(size_t)row * 1024 + 512 + kb + (e & 15)];
            }
        }
#pragma unroll
        for (int kk = 0; kk < 16; kk++) {
            float a0 = As[kk][ty * 4 + 0], a1 = As[kk][ty * 4 + 1];
            float a2 = As[kk][ty * 4 + 2], a3 = As[kk][ty * 4 + 3];
            float w0 = Bs[kk][tx * 2 + 0], w1 = Bs[kk][tx * 2 + 1];
            acc[0][0] += a0 * w0; acc[0][1] += a0 * w1;
            acc[1][0] += a1 * w0; acc[1][1] += a1 * w1;
            acc[2][0] += a2 * w0; acc[2][1] += a2 * w1;
            acc[3][0] += a3 * w0; acc[3][1] += a3 * w1;
        }
        __syncthreads();
    }
#pragma unroll
    for (int i = 0; i < 4; i++)
#pragma unroll
        for (int j = 0; j < 2; j++)
            gbuf[ty * 4 + i][tx * 2 + j] = acc[i][j];
    __syncthreads();
    const float* Xg = g_Gd + (size_t)t * NB * 2048;
#pragma unroll
    for (int i = 0; i < 2; i++) {
        int cid = tid + 256 * i;
        int b = cid >> 3, cl = cid & 7;
        int cell = cu + cl;
        const float* xb = Xg + (size_t)b * 2048;
        float gi = gbuf[b][cl] + xb[cell];
        float gf = gbuf[b][8 + cl] + xb[512 + cell];
        float gg = gbuf[b][16 + cl] + xb[1024 + cell];
        float go = gbuf[b][24 + cl] + xb[1536 + cell];
        float co = g_cd[b * H + cell];
        float cn = sigm(gf) * co + sigm(gi) * tanhf(gg);
        float hn = sigm(go) * tanhf(cn);
        g_cd[b * H + cell] = cn;
        g_H[((size_t)t * NB + b) * H + cell] = hn;
    }
}

// ---------------- skinny GEMM (M=64), bank-conflict-free weights ----------------
__global__ void __launch_bounds__(256) k_skinny(int mode, int t, const float* __restrict__ W, int ldw,
                                                const float* __restrict__ bias, int doTanh) {
    __shared__ float As[32][64];
    __shared__ float Ws[16][33];
    const float *A1, *A2 = nullptr; int lda1, lda2 = H, K1, K2; float* out; int ldo;
    if (mode == 0) { A1 = g_H + (size_t)t * NB * H; lda1 = H; K1 = H; K2 = 0; out = g_q; ldo = 1024; }
    else { A1 = g_ctx; lda1 = 1024; K1 = 1024; A2 = g_H + (size_t)t * NB * H; K2 = H; out = g_od; ldo = H; }
    int tid = threadIdx.x;
    int tn = tid & 15, tb = tid >> 4;
    int n0 = blockIdx.x * 16;
    float acc[4] = {};
    int KT = K1 + K2;
    for (int k0 = 0; k0 < KT; k0 += 32) {
        const float* src; int lda; int col;
        if (k0 < K1) { src = A1; lda = lda1; col = k0; }
        else { src = A2; lda = lda2; col = k0 - K1; }
#pragma unroll
        for (int i = 0; i < 8; i++) {
            int e = tid + 256 * i;
            int kk = e & 31, b = e >> 5;
            As[kk][b] = src[(size_t)b * lda + col + kk];
        }
#pragma unroll
        for (int i = 0; i < 2; i++) {
            int e = tid + 256 * i;
            int kk = e & 31, j = e >> 5;
            Ws[j][kk] = W[(size_t)(n0 + j) * ldw + k0 + kk];
        }
        __syncthreads();
#pragma unroll
        for (int kk = 0; kk < 32; kk++) {
            float w = Ws[tn][kk];
#pragma unroll
            for (int i = 0; i < 4; i++) acc[i] += As[kk][tb * 4 + i] * w;
        }
        __syncthreads();
    }
    int n = n0 + tn;
    float bv = bias ? bias[n] : 0.f;
#pragma unroll
    for (int i = 0; i < 4; i++) {
        float v = acc[i] + bv;
        if (doTanh) v = tanhf(v);
        out[(size_t)(tb * 4 + i) * ldo + n] = v;
    }
}

// ---------------- attention: score+softmax+context, one block per batch ----------------
__global__ void __launch_bounds__(256) k_dec_attn(const float* __restrict__ v) {
    __shared__ float sq[1024];
    __shared__ float sv[1024];
    __shared__ float sps[LS];
    int b = blockIdx.x, tid = threadIdx.x;
#pragma unroll
    for (int i = 0; i < 4; i++) {
        int k = tid + 256 * i;
        sq[k] = g_q[b * 1024 + k];
        sv[k] = v[k];
    }
    __syncthreads();
    int wid = tid >> 5, lane = tid & 31;
    for (int l = wid; l < LS; l += 8) {
        const float* hp = g_hsp + ((size_t)l * NB + b) * 1024;
        float s = 0.f;
        for (int k = lane; k < 1024; k += 32) s += sv[k] * tanhf(hp[k] + sq[k]);
#pragma unroll
        for (int o = 16; o; o >>= 1) s += __shfl_down_sync(0xffffffff, s, o);
        if (lane == 0) sps[l] = s;
    }
    __syncthreads();
    if (tid == 0) {
        float mx = -1e30f;
        for (int l = 0; l < LS; l++) mx = fmaxf(mx, sps[l]);
        float sm = 0.f;
        for (int l = 0; l < LS; l++) { float e = __expf(sps[l] - mx); sps[l] = e; sm += e; }
        float inv = 1.f / sm;
        for (int l = 0; l < LS; l++) sps[l] *= inv;
    }
    __syncthreads();
#pragma unroll
    for (int i = 0; i < 4; i++) {
        int k = tid + 256 * i;
        float acc = 0.f;
        for (int l = 0; l < LS; l++) acc += sps[l] * g_hs[((size_t)l * NB + b) * 1024 + k];
        g_ctx[b * 1024 + k] = acc;
    }
}

// ---------------- target logits (one warp per row) ----------------
__global__ void k_tgt(const int* __restrict__ ts, const float* __restrict__ oW,
                      const float* __restrict__ ob) {
    int gw = blockIdx.x * 8 + (threadIdx.x >> 5);
    int lane = threadIdx.x & 31;
    if (gw >= NROWS) return;
    int tok = ts[gw + NB];
    const float* h = g_H + (size_t)gw * H;
    const float* w = oW + (size_t)tok * H;
    float s = 0.f;
    for (int k = lane; k < H; k += 32) s += h[k] * w[k];
#pragma unroll
    for (int o = 16; o; o >>= 1) s += __shfl_down_sync(0xffffffff, s, o);
    if (lane == 0) {
        g_tgt_logit[gw] = s + ob[tok];
        g_maskv[gw] = (tok != 0) ? 1.f : 0.f;
    }
}

// ---------------- tf32 tensor-core GEMM + fused exp row-sums ----------------
__global__ void __launch_bounds__(256) k_lse(const float* __restrict__ oW,
                                             const float* __restrict__ ob) {
    __shared__ float As[16][132];
    __shared__ float Bs[16][132];
    __shared__ float red[128][8];
    int nb = blockIdx.x, mb = blockIdx.y;
    int tid = threadIdx.x;
    int lane = tid & 31, wid = tid >> 5;
    int wm = wid & 3, wn = wid >> 2;
    int mo = wm * 32, no = wn * 64;

    const float* Ab = g_H + (size_t)mb * 128 * H;
    const float* Wb = oW + (size_t)nb * 128 * H;

    int r0 = tid >> 2, q0 = tid & 3;
    int r1 = (tid + 256) >> 2, q1 = (tid + 256) & 3;

    float c[2][8][4];
#pragma unroll
    for (int mt = 0; mt < 2; mt++)
#pragma unroll
        for (int nt = 0; nt < 8; nt++)
#pragma unroll
            for (int j = 0; j < 4; j++) c[mt][nt][j] = 0.f;

    float4 pa0 = *(const float4*)&Ab[(size_t)r0 * H + q0 * 4];
    float4 pa1 = *(const float4*)&Ab[(size_t)r1 * H + q1 * 4];
    float4 pb0 = *(const float4*)&Wb[(size_t)r0 * H + q0 * 4];
    float4 pb1 = *(const float4*)&Wb[(size_t)r1 * H + q1 * 4];

    for (int kb = 0; kb < H; kb += 16) {
        As[q0 * 4 + 0][r0] = f2tf(pa0.x); As[q0 * 4 + 1][r0] = f2tf(pa0.y);
        As[q0 * 4 + 2][r0] = f2tf(pa0.z); As[q0 * 4 + 3][r0] = f2tf(pa0.w);
        As[q1 * 4 + 0][r1] = f2tf(pa1.x); As[q1 * 4 + 1][r1] = f2tf(pa1.y);
        As[q1 * 4 + 2][r1] = f2tf(pa1.z); As[q1 * 4 + 3][r1] = f2tf(pa1.w);
        Bs[q0 * 4 + 0][r0] = f2tf(pb0.x); Bs[q0 * 4 + 1][r0] = f2tf(pb0.y);
        Bs[q0 * 4 + 2][r0] = f2tf(pb0.z); Bs[q0 * 4 + 3][r0] = f2tf(pb0.w);
        Bs[q1 * 4 + 0][r1] = f2tf(pb1.x); Bs[q1 * 4 + 1][r1] = f2tf(pb1.y);
        Bs[q1 * 4 + 2][r1] = f2tf(pb1.z); Bs[q1 * 4 + 3][r1] = f2tf(pb1.w);
        __syncthreads();

        int kn = kb + 16;
        if (kn < H) {
            pa0 = *(const float4*)&Ab[(size_t)r0 * H + kn + q0 * 4];
            pa1 = *(const float4*)&Ab[(size_t)r1 * H + kn + q1 * 4];
            pb0 = *(const float4*)&Wb[(size_t)r0 * H + kn + q0 * 4];
            pb1 = *(const float4*)&Wb[(size_t)r1 * H + kn + q1 * 4];
        }

#pragma unroll
        for (int ks = 0; ks < 16; ks += 8) {
            unsigned a[2][4];
#pragma unroll
            for (int mt = 0; mt < 2; mt++) {
                int mc = mo + mt * 16 + (lane >> 2);
                a[mt][0] = __float_as_uint(As[ks + (lane & 3)][mc]);
                a[mt][1] = __float_as_uint(As[ks + (lane & 3)][mc + 8]);
                a[mt][2] = __float_as_uint(As[ks + 4 + (lane & 3)][mc]);
                a[mt][3] = __float_as_uint(As[ks + 4 + (lane & 3)][mc + 8]);
            }
#pragma unroll
            for (int nt = 0; nt < 8; nt++) {
                int nc = no + nt * 8 + (lane >> 2);
                unsigned b0 = __float_as_uint(Bs[ks + (lane & 3)][nc]);
                unsigned b1 = __float_as_uint(Bs[ks + 4 + (lane & 3)][nc]);
                mma_tf32(c[0][nt], a[0][0], a[0][1], a[0][2], a[0][3], b0, b1);
                mma_tf32(c[1][nt], a[1][0], a[1][1], a[1][2], a[1][3], b0, b1);
            }
        }
        __syncthreads();
    }

    float bv0[8], bv1[8];
#pragma unroll
    for (int nt = 0; nt < 8; nt++) {
        int n = nb * 128 + no + nt * 8 + 2 * (lane & 3);
        bv0[nt] = ob[n];
        bv1[nt] = ob[n + 1];
    }

#pragma unroll
    for (int mt = 0; mt < 2; mt++) {
        float slo = 0.f, shi = 0.f;
#pragma unroll
        for (int nt = 0; nt < 8; nt++) {
            slo += fexp(c[mt][nt][0] + bv0[nt]) + fexp(c[mt][nt][1] + bv1[nt]);
            shi += fexp(c[mt][nt][2] + bv0[nt]) + fexp(c[mt][nt][3] + bv1[nt]);
        }
        int rlo = mo + mt * 16 + (lane >> 2);
        red[rlo][wn * 4 + (lane & 3)] = slo;
        red[rlo + 8][wn * 4 + (lane & 3)] = shi;
    }
    __syncthreads();
    if (tid < 128) {
        float s = 0.f;
#pragma unroll
        for (int x = 0; x < 8; x++) s += red[tid][x];
        g_partial[((size_t)mb * 128 + tid) * NCHUNK + nb] = s;
    }
}

// ---------------- final reductions ----------------
__global__ void k_red1() {
    __shared__ float s1[256], s2[256];
    int m = blockIdx.x * 256 + threadIdx.x;
    float v = 0.f, mk = 0.f;
    if (m < NROWS) {
        float s = 0.f;
        const float* p = g_partial + (size_t)m * NCHUNK;
        for (int c = 0; c < NCHUNK; c++) s += p[c];
        mk = g_maskv[m];
        v = (logf(s) - g_tgt_logit[m]) * mk;
    }
    s1[threadIdx.x] = v; s2[threadIdx.x] = mk;
    __syncthreads();
    for (int o = 128; o; o >>= 1) {
        if (threadIdx.x < o) { s1[threadIdx.x] += s1[threadIdx.x + o]; s2[threadIdx.x] += s2[threadIdx.x + o]; }
        __syncthreads();
    }
    if (threadIdx.x == 0) { g_blk[blockIdx.x * 2] = s1[0]; g_blk[blockIdx.x * 2 + 1] = s2[0]; }
}

__global__ void k_red2(float* out) {
    if (threadIdx.x == 0) {
        float a = 0.f, b = 0.f;
        for (int i = 0; i < 12; i++) { a += g_blk[i * 2]; b += g_blk[i * 2 + 1]; }
        out[0] = a / b;
    }
}

// ---------------- launcher ----------------
extern "C" void kernel_launch(void* const* d_in, const int* in_sizes, int n_in,
                              void* d_out, int out_size) {
    const int* xs = (const int*)d_in[0];
    const int* ts = (const int*)d_in[1];
    const float* src_emb = (const float*)d_in[2];
    const float* tgt_emb = (const float*)d_in[3];
    const float* encf_Wih = (const float*)d_in[4];
    const float* encf_Whh = (const float*)d_in[5];
    const float* encf_bih = (const float*)d_in[6];
    const float* encf_bhh = (const float*)d_in[7];
    const float* encb_Wih = (const float*)d_in[8];
    const float* encb_Whh = (const float*)d_in[9];
    const float* encb_bih = (const float*)d_in[10];
    const float* encb_bhh = (const float*)d_in[11];
    const float* dec_Wih = (const float*)d_in[12];
    const float* dec_Whh = (const float*)d_in[13];
    const float* dec_bih = (const float*)d_in[14];
    const float* dec_bhh = (const float*)d_in[15];
    const float* attn_W = (const float*)d_in[16];
    const float* attn_v = (const float*)d_in[17];
    const float* lin_W = (const float*)d_in[18];
    const float* lin_b = (const float*)d_in[19];
    const float* out_W = (const float*)d_in[20];
    const float* out_b = (const float*)d_in[21];

    k_init<<<64, 256>>>();
    k_gather<<<1024, 256>>>(xs, src_emb, 0);
    k_gather<<<1024, 256>>>(ts, tgt_emb, 1);

    // input-gate precompute GEMMs (128x128 tiles, M padded to 3072)
    k_bgemm<<<dim3(16, 24), 256>>>(0, encf_Wih, 512, encf_bih, encf_bhh, 512);
    k_bgemm<<<dim3(16, 24), 256>>>(1, encb_Wih, 512, encb_bih, encb_bhh, 512);
    k_bgemm<<<dim3(16, 24), 256>>>(2, dec_Wih, 1024, dec_bih, dec_bhh, 512);

    // encoder recurrence (both directions per launch)
    for (int t = 0; t < LS; t++)
        k_enc_step<<<dim3(64, 2), 256>>>(t, encf_Whh, encb_Whh);

    // hs_proj = hs @ Wk^T   (Wk = attn_W[:, 512:], ld 1536)
    k_bgemm<<<dim3(8, 24), 256>>>(3, attn_W + 512, 1536, nullptr, nullptr, 1024);

    // decoder recurrence
    for (int t = 0; t < LTm1; t++) {
        k_dec_gates<<<64, 256>>>(t, dec_Wih, dec_Whh);
        k_skinny<<<64, 256>>>(0, t, attn_W, 1536, nullptr, 0);      // q = h @ Wq^T
        k_dec_attn<<<64, 256>>>(attn_v);
        k_skinny<<<32, 256>>>(1, t, lin_W, 1536, lin_b, 1);          // o = tanh([ctx,h]@lin^T+b)
    }

    // output projection + NLL
    k_tgt<<<376, 256>>>(ts, out_W, out_b);
    k_lse<<<dim3(NCHUNK, NROWS_PAD / 128), 256>>>(out_W, out_b);
    k_red1<<<12, 256>>>();
    k_red2<<<1, 32>>>((float*)d_out);
}

// round 7
// speedup vs baseline: 3.1323x; 1.7735x over previous
#include <cuda_runtime.h>
#include <math.h>

#define LS 48
#define LTm1 47
#define NB 64      // batch
#define E 512
#define H 512
#define VT 32000
#define NROWS 3008      // 47*64 decoder (step,batch) rows
#define NROWS_PAD 3072  // padded to multiple of 128
#define NCHUNK 250      // 32000/128

// ---------------- device scratch (static, allowed) ----------------
__device__ float g_zero[NB * H];
__device__ float g_embs_src[LS * NB * E];
__device__ float g_embs_tgt[NROWS_PAD * E];     // padded to 3072 rows
__device__ float g_Xf[LS * NB * 2048];
__device__ float g_Xb[LS * NB * 2048];
__device__ float g_Gd[NROWS_PAD * 2048];        // padded to 3072 rows
__device__ float g_hs[LS * NB * 1024];    // [t][b][1024] fwd||bwd
__device__ float g_hsp[LS * NB * 1024];   // hs_proj [l][b][1024]
__device__ float g_cf[NB * H];
__device__ float g_cb[NB * H];
__device__ float g_cd[NB * H];
__device__ float g_od[NB * H];
__device__ float g_q[NB * 1024];
__device__ float g_ctx[NB * 1024];
__device__ float g_H[NROWS_PAD * H];      // decoder h history (rows m=t*64+b)
__device__ float g_tgt_logit[NROWS];
__device__ float g_maskv[NROWS];
__device__ float g_partial[NROWS_PAD * NCHUNK];
__device__ float g_blk[24];

__device__ __forceinline__ float sigm(float x) { return 1.f / (1.f + __expf(-x)); }

__device__ __forceinline__ float ftanh(float x) {
    float y;
    asm("tanh.approx.f32 %0, %1;" : "=f"(y) : "f"(x));
    return y;
}

__device__ __forceinline__ float f2tf(float x) {
    unsigned u;
    asm("cvt.rna.tf32.f32 %0, %1;" : "=r"(u) : "f"(x));
    return __uint_as_float(u);
}

// fast exp on the FMA pipe
__device__ __forceinline__ float fexp(float x) {
    float y = x * 1.44269504f;
    float fl = floorf(y);
    float f = y - fl;
    float p = fmaf(f, 0.0013333558f, 0.0096181291f);
    p = fmaf(f, p, 0.055504109f);
    p = fmaf(f, p, 0.24022651f);
    p = fmaf(f, p, 0.69314718f);
    p = fmaf(f, p, 1.0f);
    int e = (int)fl;
    return p * __int_as_float((e + 127) << 23);
}

__device__ __forceinline__ void mma_tf32(float* c, unsigned a0, unsigned a1, unsigned a2,
                                         unsigned a3, unsigned b0, unsigned b1) {
    asm volatile(
        "mma.sync.aligned.m16n8k8.row.col.f32.tf32.tf32.f32 "
        "{%0,%1,%2,%3},{%4,%5,%6,%7},{%8,%9},{%0,%1,%2,%3};"
        : "+f"(c[0]), "+f"(c[1]), "+f"(c[2]), "+f"(c[3])
        : "r"(a0), "r"(a1), "r"(a2), "r"(a3), "r"(b0), "r"(b1));
}

// ---------------- init ----------------
__global__ void k_init() {
    int i = blockIdx.x * blockDim.x + threadIdx.x;
    int n = NB * H;   // 32768
    for (int j = i; j < n; j += gridDim.x * blockDim.x) {
        g_zero[j] = 0.f; g_cf[j] = 0.f; g_cb[j] = 0.f;
        g_cd[j] = 0.f; g_od[j] = 0.f;
        g_H[NROWS * H + j] = 0.f;           // pad rows 3008..3071
        g_embs_tgt[NROWS * E + j] = 0.f;
    }
}

// ---------------- embedding gather ----------------
__global__ void k_gather(const int* __restrict__ tok, const float* __restrict__ emb, int mode) {
    float* out = mode ? g_embs_tgt : g_embs_src;
    int rows = mode ? (LTm1 * NB) : (LS * NB);
    int n4 = rows * (E / 4);
    const float4* e4 = (const float4*)emb;
    float4* o4 = (float4*)out;
    for (int j = blockIdx.x * blockDim.x + threadIdx.x; j < n4; j += gridDim.x * blockDim.x) {
        int r = j >> 7;
        int c = j & 127;
        o4[j] = e4[(size_t)tok[r] * 128 + c];
    }
}

// ---------------- big fp32 GEMM (precompute): 128x128x16 tile, 8x8 micro ----------------
__global__ void __launch_bounds__(256) k_bgemm(int mode, const float* __restrict__ W, int ldw,
                                               const float* __restrict__ b1, const float* __restrict__ b2,
                                               int K) {
    __shared__ float As[16][136];
    __shared__ float Bs[16][136];
    const float* A; int lda; float* C; int ldc;
    switch (mode) {
        case 0: A = g_embs_src; lda = E;    C = g_Xf;  ldc = 2048; break;
        case 1: A = g_embs_src; lda = E;    C = g_Xb;  ldc = 2048; break;
        case 2: A = g_embs_tgt; lda = E;    C = g_Gd;  ldc = 2048; break;
        default: A = g_hs;      lda = 1024; C = g_hsp; ldc = 1024; break;
    }
    int nb = blockIdx.x, mb = blockIdx.y;
    int tid = threadIdx.x;
    int tx = tid & 15, ty = tid >> 4;

    const float* Ab = A + (size_t)mb * 128 * lda;
    const float* Wb = W + (size_t)nb * 128 * ldw;

    int r0 = tid >> 2, q0 = tid & 3;
    int r1 = (tid + 256) >> 2, q1 = (tid + 256) & 3;

    float acc[8][8];
#pragma unroll
    for (int i = 0; i < 8; i++)
#pragma unroll
        for (int j = 0; j < 8; j++) acc[i][j] = 0.f;

    float4 pa0 = *(const float4*)&Ab[(size_t)r0 * lda + q0 * 4];
    float4 pa1 = *(const float4*)&Ab[(size_t)r1 * lda + q1 * 4];
    float4 pb0 = *(const float4*)&Wb[(size_t)r0 * ldw + q0 * 4];
    float4 pb1 = *(const float4*)&Wb[(size_t)r1 * ldw + q1 * 4];

    for (int kb = 0; kb < K; kb += 16) {
        As[q0 * 4 + 0][r0] = pa0.x; As[q0 * 4 + 1][r0] = pa0.y;
        As[q0 * 4 + 2][r0] = pa0.z; As[q0 * 4 + 3][r0] = pa0.w;
        As[q1 * 4 + 0][r1] = pa1.x; As[q1 * 4 + 1][r1] = pa1.y;
        As[q1 * 4 + 2][r1] = pa1.z; As[q1 * 4 + 3][r1] = pa1.w;
        Bs[q0 * 4 + 0][r0] = pb0.x; Bs[q0 * 4 + 1][r0] = pb0.y;
        Bs[q0 * 4 + 2][r0] = pb0.z; Bs[q0 * 4 + 3][r0] = pb0.w;
        Bs[q1 * 4 + 0][r1] = pb1.x; Bs[q1 * 4 + 1][r1] = pb1.y;
        Bs[q1 * 4 + 2][r1] = pb1.z; Bs[q1 * 4 + 3][r1] = pb1.w;
        __syncthreads();

        int kn = kb + 16;
        if (kn < K) {
            pa0 = *(const float4*)&Ab[(size_t)r0 * lda + kn + q0 * 4];
            pa1 = *(const float4*)&Ab[(size_t)r1 * lda + kn + q1 * 4];
            pb0 = *(const float4*)&Wb[(size_t)r0 * ldw + kn + q0 * 4];
            pb1 = *(const float4*)&Wb[(size_t)r1 * ldw + kn + q1 * 4];
        }

#pragma unroll
        for (int kk = 0; kk < 16; kk++) {
            float4 a0 = *(const float4*)&As[kk][ty * 8];
            float4 a1 = *(const float4*)&As[kk][ty * 8 + 4];
            float4 w0 = *(const float4*)&Bs[kk][tx * 8];
            float4 w1 = *(const float4*)&Bs[kk][tx * 8 + 4];
            float av[8] = {a0.x, a0.y, a0.z, a0.w, a1.x, a1.y, a1.z, a1.w};
            float wv[8] = {w0.x, w0.y, w0.z, w0.w, w1.x, w1.y, w1.z, w1.w};
#pragma unroll
            for (int i = 0; i < 8; i++)
#pragma unroll
                for (int j = 0; j < 8; j++) acc[i][j] = fmaf(av[i], wv[j], acc[i][j]);
        }
        __syncthreads();
    }

    float bias[8];
#pragma unroll
    for (int j = 0; j < 8; j++) {
        int n = nb * 128 + tx * 8 + j;
        float v = 0.f;
        if (b1) v += b1[n];
        if (b2) v += b2[n];
        bias[j] = v;
    }
#pragma unroll
    for (int i = 0; i < 8; i++) {
        int r = mb * 128 + ty * 8 + i;
#pragma unroll
        for (int j = 0; j < 8; j++) {
            int n = nb * 128 + tx * 8 + j;
            C[(size_t)r * ldc + n] = acc[i][j] + bias[j];
        }
    }
}

// ============================================================================
// tf32 MMA recurrent kernels. Common tile pattern (verified in k_lse):
//   As[k][m] (pad 72), Bs[k][n] (pad 24); warp (mw=wid&3, nw=wid>>2) owns a
//   16x8 output tile; frags: a0=(k,m) a1=(k,m+8) a2=(k+4,m) a3=(k+4,m+8),
//   b0=(k,n) b1=(k+4,n); c: rows lane>>2/+8, cols 2*(lane&3)/+1.
// ============================================================================

// ---------------- encoder step (tf32): grid (128, 2), 4 cells/block ----------------
__global__ void __launch_bounds__(256) k_enc_mma(int t, const float* __restrict__ Whh_f,
                                                 const float* __restrict__ Whh_b) {
    __shared__ float As[16][72];
    __shared__ float Bs[16][24];
    __shared__ float gbuf[64][17];
    int dir = blockIdx.y;
    int cu = blockIdx.x * 4;
    int tid = threadIdx.x, lane = tid & 31, wid = tid >> 5;
    int mw = wid & 3, nw = wid >> 2;
    const float* Whh = dir ? Whh_b : Whh_f;
    const float* hprev; int ldh;
    if (t == 0) { hprev = g_zero; ldh = H; }
    else if (dir == 0) { hprev = g_hs + (size_t)(t - 1) * NB * 1024; ldh = 1024; }
    else { hprev = g_hs + (size_t)(LS - t) * NB * 1024 + 512; ldh = 1024; }

    int ar = tid >> 2, aq = tid & 3;                       // A loader: batch, k-quad
    int jrow = tid >> 4, jk = tid & 15;                    // B loader: col j, k
    int grow = ((jrow >> 2) << 9) + cu + (jrow & 3);       // weight row for col j

    float acc[4] = {0.f, 0.f, 0.f, 0.f};
    float4 pa = *(const float4*)&hprev[(size_t)ar * ldh + aq * 4];
    float pb = Whh[(size_t)grow * H + jk];

    for (int kb = 0; kb < H; kb += 16) {
        As[aq * 4 + 0][ar] = f2tf(pa.x); As[aq * 4 + 1][ar] = f2tf(pa.y);
        As[aq * 4 + 2][ar] = f2tf(pa.z); As[aq * 4 + 3][ar] = f2tf(pa.w);
        Bs[jk][jrow] = f2tf(pb);
        __syncthreads();
        int kn = kb + 16;
        if (kn < H) {
            pa = *(const float4*)&hprev[(size_t)ar * ldh + kn + aq * 4];
            pb = Whh[(size_t)grow * H + kn + jk];
        }
        int mc = mw * 16 + (lane >> 2);
        int nc = nw * 8 + (lane >> 2);
#pragma unroll
        for (int ks = 0; ks < 16; ks += 8) {
            unsigned a0 = __float_as_uint(As[ks + (lane & 3)][mc]);
            unsigned a1 = __float_as_uint(As[ks + (lane & 3)][mc + 8]);
            unsigned a2 = __float_as_uint(As[ks + 4 + (lane & 3)][mc]);
            unsigned a3 = __float_as_uint(As[ks + 4 + (lane & 3)][mc + 8]);
            unsigned b0 = __float_as_uint(Bs[ks + (lane & 3)][nc]);
            unsigned b1 = __float_as_uint(Bs[ks + 4 + (lane & 3)][nc]);
            mma_tf32(acc, a0, a1, a2, a3, b0, b1);
        }
        __syncthreads();
    }
    {
        int m = mw * 16 + (lane >> 2);
        int n = nw * 8 + 2 * (lane & 3);
        gbuf[m][n] = acc[0]; gbuf[m][n + 1] = acc[1];
        gbuf[m + 8][n] = acc[2]; gbuf[m + 8][n + 1] = acc[3];
    }
    __syncthreads();

    const float* Xg = dir ? (g_Xb + (size_t)(LS - 1 - t) * NB * 2048)
                          : (g_Xf + (size_t)t * NB * 2048);
    float* cst = dir ? g_cb : g_cf;
    float* hs_out = dir ? (g_hs + (size_t)(LS - 1 - t) * NB * 1024 + 512)
                        : (g_hs + (size_t)t * NB * 1024);
    {
        int b = tid & 63, cl = tid >> 6;
        int cell = cu + cl;
        const float* xb = Xg + (size_t)b * 2048;
        float gi = gbuf[b][cl] + xb[cell];
        float gf = gbuf[b][4 + cl] + xb[512 + cell];
        float gg = gbuf[b][8 + cl] + xb[1024 + cell];
        float go = gbuf[b][12 + cl] + xb[1536 + cell];
        float co = cst[b * H + cell];
        float cn = sigm(gf) * co + sigm(gi) * tanhf(gg);
        float hn = sigm(go) * tanhf(cn);
        cst[b * H + cell] = cn;
        hs_out[(size_t)b * 1024 + cell] = hn;
    }
}

// ---------------- decoder gates (tf32): grid 128, 4 cells/block, K=1024 ----------------
__global__ void __launch_bounds__(256) k_dec_mma(int t, const float* __restrict__ Wih,
                                                 const float* __restrict__ Whh) {
    __shared__ float As[16][72];
    __shared__ float Bs[16][24];
    __shared__ float gbuf[64][17];
    int cu = blockIdx.x * 4;
    int tid = threadIdx.x, lane = tid & 31, wid = tid >> 5;
    int mw = wid & 3, nw = wid >> 2;
    const float* hprev = (t == 0) ? g_zero : (g_H + (size_t)(t - 1) * NB * H);

    int ar = tid >> 2, aq = tid & 3;
    int jrow = tid >> 4, jk = tid & 15;
    int grow = ((jrow >> 2) << 9) + cu + (jrow & 3);

    float acc[4] = {0.f, 0.f, 0.f, 0.f};
    // slice sl: part = sl>>5 (0: o x Wih[:,512+k], 1: h x Whh), kcol = (sl&31)*16
    float4 pa = *(const float4*)&g_od[(size_t)ar * H + aq * 4];
    float pb = Wih[(size_t)grow * 1024 + 512 + jk];

    for (int sl = 0; sl < 64; sl++) {
        As[aq * 4 + 0][ar] = f2tf(pa.x); As[aq * 4 + 1][ar] = f2tf(pa.y);
        As[aq * 4 + 2][ar] = f2tf(pa.z); As[aq * 4 + 3][ar] = f2tf(pa.w);
        Bs[jk][jrow] = f2tf(pb);
        __syncthreads();
        int ns = sl + 1;
        if (ns < 64) {
            int part = ns >> 5;
            int kcol = (ns & 31) * 16;
            const float* Ain = part ? hprev : g_od;
            pa = *(const float4*)&Ain[(size_t)ar * H + kcol + aq * 4];
            pb = part ? Whh[(size_t)grow * H + kcol + jk]
                      : Wih[(size_t)grow * 1024 + 512 + kcol + jk];
        }
        int mc = mw * 16 + (lane >> 2);
        int nc = nw * 8 + (lane >> 2);
#pragma unroll
        for (int ks = 0; ks < 16; ks += 8) {
            unsigned a0 = __float_as_uint(As[ks + (lane & 3)][mc]);
            unsigned a1 = __float_as_uint(As[ks + (lane & 3)][mc + 8]);
            unsigned a2 = __float_as_uint(As[ks + 4 + (lane & 3)][mc]);
            unsigned a3 = __float_as_uint(As[ks + 4 + (lane & 3)][mc + 8]);
            unsigned b0 = __float_as_uint(Bs[ks + (lane & 3)][nc]);
            unsigned b1 = __float_as_uint(Bs[ks + 4 + (lane & 3)][nc]);
            mma_tf32(acc, a0, a1, a2, a3, b0, b1);
        }
        __syncthreads();
    }
    {
        int m = mw * 16 + (lane >> 2);
        int n = nw * 8 + 2 * (lane & 3);
        gbuf[m][n] = acc[0]; gbuf[m][n + 1] = acc[1];
        gbuf[m + 8][n] = acc[2]; gbuf[m + 8][n + 1] = acc[3];
    }
    __syncthreads();
    {
        int b = tid & 63, cl = tid >> 6;
        int cell = cu + cl;
        const float* xb = g_Gd + (size_t)t * NB * 2048 + (size_t)b * 2048;
        float gi = gbuf[b][cl] + xb[cell];
        float gf = gbuf[b][4 + cl] + xb[512 + cell];
        float gg = gbuf[b][8 + cl] + xb[1024 + cell];
        float go = gbuf[b][12 + cl] + xb[1536 + cell];
        float co = g_cd[b * H + cell];
        float cn = sigm(gf) * co + sigm(gi) * tanhf(gg);
        float hn = sigm(go) * tanhf(cn);
        g_cd[b * H + cell] = cn;
        g_H[((size_t)t * NB + b) * H + cell] = hn;
    }
}

// ---------------- q projection (tf32): 64 blocks x 16 cols, K=512 ----------------
__global__ void __launch_bounds__(256) k_q_mma(int t, const float* __restrict__ attn_W) {
    __shared__ float As[16][72];
    __shared__ float Bs[16][24];
    int n0 = blockIdx.x * 16;
    int tid = threadIdx.x, lane = tid & 31, wid = tid >> 5;
    int mw = wid & 3, nw = wid >> 2;
    const float* A = g_H + (size_t)t * NB * H;

    int ar = tid >> 2, aq = tid & 3;
    int jrow = tid >> 4, jk = tid & 15;
    const float* Wr = attn_W + (size_t)(n0 + jrow) * 1536;   // Wq rows, cols 0..511

    float acc[4] = {0.f, 0.f, 0.f, 0.f};
    float4 pa = *(const float4*)&A[(size_t)ar * H + aq * 4];
    float pb = Wr[jk];

    for (int kb = 0; kb < H; kb += 16) {
        As[aq * 4 + 0][ar] = f2tf(pa.x); As[aq * 4 + 1][ar] = f2tf(pa.y);
        As[aq * 4 + 2][ar] = f2tf(pa.z); As[aq * 4 + 3][ar] = f2tf(pa.w);
        Bs[jk][jrow] = f2tf(pb);
        __syncthreads();
        int kn = kb + 16;
        if (kn < H) {
            pa = *(const float4*)&A[(size_t)ar * H + kn + aq * 4];
            pb = Wr[kn + jk];
        }
        int mc = mw * 16 + (lane >> 2);
        int nc = nw * 8 + (lane >> 2);
#pragma unroll
        for (int ks = 0; ks < 16; ks += 8) {
            unsigned a0 = __float_as_uint(As[ks + (lane & 3)][mc]);
            unsigned a1 = __float_as_uint(As[ks + (lane & 3)][mc + 8]);
            unsigned a2 = __float_as_uint(As[ks + 4 + (lane & 3)][mc]);
            unsigned a3 = __float_as_uint(As[ks + 4 + (lane & 3)][mc + 8]);
            unsigned b0 = __float_as_uint(Bs[ks + (lane & 3)][nc]);
            unsigned b1 = __float_as_uint(Bs[ks + 4 + (lane & 3)][nc]);
            mma_tf32(acc, a0, a1, a2, a3, b0, b1);
        }
        __syncthreads();
    }
    int m = mw * 16 + (lane >> 2);
    int n = n0 + nw * 8 + 2 * (lane & 3);
    g_q[(size_t)m * 1024 + n] = acc[0];
    g_q[(size_t)m * 1024 + n + 1] = acc[1];
    g_q[(size_t)(m + 8) * 1024 + n] = acc[2];
    g_q[(size_t)(m + 8) * 1024 + n + 1] = acc[3];
}

// ---------------- o projection (tf32): 32 blocks x 16 cols, K=1536 ----------------
__global__ void __launch_bounds__(256) k_o_mma(int t, const float* __restrict__ lin_W,
                                               const float* __restrict__ lin_b) {
    __shared__ float As[16][72];
    __shared__ float Bs[16][24];
    int n0 = blockIdx.x * 16;
    int tid = threadIdx.x, lane = tid & 31, wid = tid >> 5;
    int mw = wid & 3, nw = wid >> 2;
    const float* hA = g_H + (size_t)t * NB * H;

    int ar = tid >> 2, aq = tid & 3;
    int jrow = tid >> 4, jk = tid & 15;
    const float* Wr = lin_W + (size_t)(n0 + jrow) * 1536;

    float acc[4] = {0.f, 0.f, 0.f, 0.f};
    // slice sl<64: ctx (ld 1024, col sl*16); sl>=64: h (ld 512, col (sl-64)*16)
    float4 pa = *(const float4*)&g_ctx[(size_t)ar * 1024 + aq * 4];
    float pb = Wr[jk];

    for (int sl = 0; sl < 96; sl++) {
        As[aq * 4 + 0][ar] = f2tf(pa.x); As[aq * 4 + 1][ar] = f2tf(pa.y);
        As[aq * 4 + 2][ar] = f2tf(pa.z); As[aq * 4 + 3][ar] = f2tf(pa.w);
        Bs[jk][jrow] = f2tf(pb);
        __syncthreads();
        int ns = sl + 1;
        if (ns < 96) {
            if (ns < 64)
                pa = *(const float4*)&g_ctx[(size_t)ar * 1024 + ns * 16 + aq * 4];
            else
                pa = *(const float4*)&hA[(size_t)ar * H + (ns - 64) * 16 + aq * 4];
            pb = Wr[ns * 16 + jk];
        }
        int mc = mw * 16 + (lane >> 2);
        int nc = nw * 8 + (lane >> 2);
#pragma unroll
        for (int ks = 0; ks < 16; ks += 8) {
            unsigned a0 = __float_as_uint(As[ks + (lane & 3)][mc]);
            unsigned a1 = __float_as_uint(As[ks + (lane & 3)][mc + 8]);
            unsigned a2 = __float_as_uint(As[ks + 4 + (lane & 3)][mc]);
            unsigned a3 = __float_as_uint(As[ks + 4 + (lane & 3)][mc + 8]);
            unsigned b0 = __float_as_uint(Bs[ks + (lane & 3)][nc]);
            unsigned b1 = __float_as_uint(Bs[ks + 4 + (lane & 3)][nc]);
            mma_tf32(acc, a0, a1, a2, a3, b0, b1);
        }
        __syncthreads();
    }
    int m = mw * 16 + (lane >> 2);
    int n = n0 + nw * 8 + 2 * (lane & 3);
    float b0v = lin_b[n], b1v = lin_b[n + 1];
    g_od[(size_t)m * H + n] = tanhf(acc[0] + b0v);
    g_od[(size_t)m * H + n + 1] = tanhf(acc[1] + b1v);
    g_od[(size_t)(m + 8) * H + n] = tanhf(acc[2] + b0v);
    g_od[(size_t)(m + 8) * H + n + 1] = tanhf(acc[3] + b1v);
}

// ---------------- attention: score+softmax+context, one block per batch ----------------
__global__ void __launch_bounds__(256) k_dec_attn(const float* __restrict__ v) {
    __shared__ float sq[1024];
    __shared__ float sv[1024];
    __shared__ float sps[LS];
    int b = blockIdx.x, tid = threadIdx.x;
#pragma unroll
    for (int i = 0; i < 4; i++) {
        int k = tid + 256 * i;
        sq[k] = g_q[b * 1024 + k];
        sv[k] = v[k];
    }
    __syncthreads();
    int wid = tid >> 5, lane = tid & 31;
    for (int l = wid; l < LS; l += 8) {
        const float* hp = g_hsp + ((size_t)l * NB + b) * 1024;
        float s = 0.f;
        for (int k = lane; k < 1024; k += 32) s += sv[k] * ftanh(hp[k] + sq[k]);
#pragma unroll
        for (int o = 16; o; o >>= 1) s += __shfl_down_sync(0xffffffff, s, o);
        if (lane == 0) sps[l] = s;
    }
    __syncthreads();
    if (tid == 0) {
        float mx = -1e30f;
        for (int l = 0; l < LS; l++) mx = fmaxf(mx, sps[l]);
        float sm = 0.f;
        for (int l = 0; l < LS; l++) { float e = __expf(sps[l] - mx); sps[l] = e; sm += e; }
        float inv = 1.f / sm;
        for (int l = 0; l < LS; l++) sps[l] *= inv;
    }
    __syncthreads();
#pragma unroll
    for (int i = 0; i < 4; i++) {
        int k = tid + 256 * i;
        float acc = 0.f;
        for (int l = 0; l < LS; l++) acc += sps[l] * g_hs[((size_t)l * NB + b) * 1024 + k];
        g_ctx[b * 1024 + k] = acc;
    }
}

// ---------------- target logits (one warp per row) ----------------
__global__ void k_tgt(const int* __restrict__ ts, const float* __restrict__ oW,
                      const float* __restrict__ ob) {
    int gw = blockIdx.x * 8 + (threadIdx.x >> 5);
    int lane = threadIdx.x & 31;
    if (gw >= NROWS) return;
    int tok = ts[gw + NB];
    const float* h = g_H + (size_t)gw * H;
    const float* w = oW + (size_t)tok * H;
    float s = 0.f;
    for (int k = lane; k < H; k += 32) s += h[k] * w[k];
#pragma unroll
    for (int o = 16; o; o >>= 1) s += __shfl_down_sync(0xffffffff, s, o);
    if (lane == 0) {
        g_tgt_logit[gw] = s + ob[tok];
        g_maskv[gw] = (tok != 0) ? 1.f : 0.f;
    }
}

// ---------------- tf32 tensor-core GEMM + fused exp row-sums ----------------
__global__ void __launch_bounds__(256) k_lse(const float* __restrict__ oW,
                                             const float* __restrict__ ob) {
    __shared__ float As[16][136];
    __shared__ float Bs[16][136];
    __shared__ float red[128][8];
    int nb = blockIdx.x, mb = blockIdx.y;
    int tid = threadIdx.x;
    int lane = tid & 31, wid = tid >> 5;
    int wm = wid & 3, wn = wid >> 2;
    int mo = wm * 32, no = wn * 64;

    const float* Ab = g_H + (size_t)mb * 128 * H;
    const float* Wb = oW + (size_t)nb * 128 * H;

    int r0 = tid >> 2, q0 = tid & 3;
    int r1 = (tid + 256) >> 2, q1 = (tid + 256) & 3;

    float c[2][8][4];
#pragma unroll
    for (int mt = 0; mt < 2; mt++)
#pragma unroll
        for (int nt = 0; nt < 8; nt++)
#pragma unroll
            for (int j = 0; j < 4; j++) c[mt][nt][j] = 0.f;

    float4 pa0 = *(const float4*)&Ab[(size_t)r0 * H + q0 * 4];
    float4 pa1 = *(const float4*)&Ab[(size_t)r1 * H + q1 * 4];
    float4 pb0 = *(const float4*)&Wb[(size_t)r0 * H + q0 * 4];
    float4 pb1 = *(const float4*)&Wb[(size_t)r1 * H + q1 * 4];

    for (int kb = 0; kb < H; kb += 16) {
        As[q0 * 4 + 0][r0] = f2tf(pa0.x); As[q0 * 4 + 1][r0] = f2tf(pa0.y);
        As[q0 * 4 + 2][r0] = f2tf(pa0.z); As[q0 * 4 + 3][r0] = f2tf(pa0.w);
        As[q1 * 4 + 0][r1] = f2tf(pa1.x); As[q1 * 4 + 1][r1] = f2tf(pa1.y);
        As[q1 * 4 + 2][r1] = f2tf(pa1.z); As[q1 * 4 + 3][r1] = f2tf(pa1.w);
        Bs[q0 * 4 + 0][r0] = f2tf(pb0.x); Bs[q0 * 4 + 1][r0] = f2tf(pb0.y);
        Bs[q0 * 4 + 2][r0] = f2tf(pb0.z); Bs[q0 * 4 + 3][r0] = f2tf(pb0.w);
        Bs[q1 * 4 + 0][r1] = f2tf(pb1.x); Bs[q1 * 4 + 1][r1] = f2tf(pb1.y);
        Bs[q1 * 4 + 2][r1] = f2tf(pb1.z); Bs[q1 * 4 + 3][r1] = f2tf(pb1.w);
        __syncthreads();

        int kn = kb + 16;
        if (kn < H) {
            pa0 = *(const float4*)&Ab[(size_t)r0 * H + kn + q0 * 4];
            pa1 = *(const float4*)&Ab[(size_t)r1 * H + kn + q1 * 4];
            pb0 = *(const float4*)&Wb[(size_t)r0 * H + kn + q0 * 4];
            pb1 = *(const float4*)&Wb[(size_t)r1 * H + kn + q1 * 4];
        }

#pragma unroll
        for (int ks = 0; ks < 16; ks += 8) {
            unsigned a[2][4];
#pragma unroll
            for (int mt = 0; mt < 2; mt++) {
                int mc = mo + mt * 16 + (lane >> 2);
                a[mt][0] = __float_as_uint(As[ks + (lane & 3)][mc]);
                a[mt][1] = __float_as_uint(As[ks + (lane & 3)][mc + 8]);
                a[mt][2] = __float_as_uint(As[ks + 4 + (lane & 3)][mc]);
                a[mt][3] = __float_as_uint(As[ks + 4 + (lane & 3)][mc + 8]);
            }
#pragma unroll
            for (int nt = 0; nt < 8; nt++) {
                int nc = no + nt * 8 + (lane >> 2);
                unsigned b0 = __float_as_uint(Bs[ks + (lane & 3)][nc]);
                unsigned b1 = __float_as_uint(Bs[ks + 4 + (lane & 3)][nc]);
                mma_tf32(c[0][nt], a[0][0], a[0][1], a[0][2], a[0][3], b0, b1);
                mma_tf32(c[1][nt], a[1][0], a[1][1], a[1][2], a[1][3], b0, b1);
            }
        }
        __syncthreads();
    }

    float bv0[8], bv1[8];
#pragma unroll
    for (int nt = 0; nt < 8; nt++) {
        int n = nb * 128 + no + nt * 8 + 2 * (lane & 3);
        bv0[nt] = ob[n];
        bv1[nt] = ob[n + 1];
    }

#pragma unroll
    for (int mt = 0; mt < 2; mt++) {
        float slo = 0.f, shi = 0.f;
#pragma unroll
        for (int nt = 0; nt < 8; nt++) {
            slo += fexp(c[mt][nt][0] + bv0[nt]) + fexp(c[mt][nt][1] + bv1[nt]);
            shi += fexp(c[mt][nt][2] + bv0[nt]) + fexp(c[mt][nt][3] + bv1[nt]);
        }
        int rlo = mo + mt * 16 + (lane >> 2);
        red[rlo][wn * 4 + (lane & 3)] = slo;
        red[rlo + 8][wn * 4 + (lane & 3)] = shi;
    }
    __syncthreads();
    if (tid < 128) {
        float s = 0.f;
#pragma unroll
        for (int x = 0; x < 8; x++) s += red[tid][x];
        g_partial[((size_t)mb * 128 + tid) * NCHUNK + nb] = s;
    }
}

// ---------------- final reductions ----------------
__global__ void k_red1() {
    __shared__ float s1[256], s2[256];
    int m = blockIdx.x * 256 + threadIdx.x;
    float v = 0.f, mk = 0.f;
    if (m < NROWS) {
        float s = 0.f;
        const float* p = g_partial + (size_t)m * NCHUNK;
        for (int c = 0; c < NCHUNK; c++) s += p[c];
        mk = g_maskv[m];
        v = (logf(s) - g_tgt_logit[m]) * mk;
    }
    s1[threadIdx.x] = v; s2[threadIdx.x] = mk;
    __syncthreads();
    for (int o = 128; o; o >>= 1) {
        if (threadIdx.x < o) { s1[threadIdx.x] += s1[threadIdx.x + o]; s2[threadIdx.x] += s2[threadIdx.x + o]; }
        __syncthreads();
    }
    if (threadIdx.x == 0) { g_blk[blockIdx.x * 2] = s1[0]; g_blk[blockIdx.x * 2 + 1] = s2[0]; }
}

__global__ void k_red2(float* out) {
    if (threadIdx.x == 0) {
        float a = 0.f, b = 0.f;
        for (int i = 0; i < 12; i++) { a += g_blk[i * 2]; b += g_blk[i * 2 + 1]; }
        out[0] = a / b;
    }
}

// ---------------- launcher ----------------
extern "C" void kernel_launch(void* const* d_in, const int* in_sizes, int n_in,
                              void* d_out, int out_size) {
    const int* xs = (const int*)d_in[0];
    const int* ts = (const int*)d_in[1];
    const float* src_emb = (const float*)d_in[2];
    const float* tgt_emb = (const float*)d_in[3];
    const float* encf_Wih = (const float*)d_in[4];
    const float* encf_Whh = (const float*)d_in[5];
    const float* encf_bih = (const float*)d_in[6];
    const float* encf_bhh = (const float*)d_in[7];
    const float* encb_Wih = (const float*)d_in[8];
    const float* encb_Whh = (const float*)d_in[9];
    const float* encb_bih = (const float*)d_in[10];
    const float* encb_bhh = (const float*)d_in[11];
    const float* dec_Wih = (const float*)d_in[12];
    const float* dec_Whh = (const float*)d_in[13];
    const float* dec_bih = (const float*)d_in[14];
    const float* dec_bhh = (const float*)d_in[15];
    const float* attn_W = (const float*)d_in[16];
    const float* attn_v = (const float*)d_in[17];
    const float* lin_W = (const float*)d_in[18];
    const float* lin_b = (const float*)d_in[19];
    const float* out_W = (const float*)d_in[20];
    const float* out_b = (const float*)d_in[21];

    k_init<<<64, 256>>>();
    k_gather<<<1024, 256>>>(xs, src_emb, 0);
    k_gather<<<1024, 256>>>(ts, tgt_emb, 1);

    // input-gate precompute GEMMs (128x128 tiles)
    k_bgemm<<<dim3(16, 24), 256>>>(0, encf_Wih, 512, encf_bih, encf_bhh, 512);
    k_bgemm<<<dim3(16, 24), 256>>>(1, encb_Wih, 512, encb_bih, encb_bhh, 512);
    k_bgemm<<<dim3(16, 24), 256>>>(2, dec_Wih, 1024, dec_bih, dec_bhh, 512);

    // encoder recurrence (tf32 MMA, both directions per launch)
    for (int t = 0; t < LS; t++)
        k_enc_mma<<<dim3(128, 2), 256>>>(t, encf_Whh, encb_Whh);

    // hs_proj = hs @ Wk^T   (Wk = attn_W[:, 512:], ld 1536)
    k_bgemm<<<dim3(8, 24), 256>>>(3, attn_W + 512, 1536, nullptr, nullptr, 1024);

    // decoder recurrence (tf32 MMA)
    for (int t = 0; t < LTm1; t++) {
        k_dec_mma<<<128, 256>>>(t, dec_Wih, dec_Whh);
        k_q_mma<<<64, 256>>>(t, attn_W);
        k_dec_attn<<<64, 256>>>(attn_v);
        k_o_mma<<<32, 256>>>(t, lin_W, lin_b);
    }

    // output projection + NLL
    k_tgt<<<376, 256>>>(ts, out_W, out_b);
    k_lse<<<dim3(NCHUNK, NROWS_PAD / 128), 256>>>(out_W, out_b);
    k_red1<<<12, 256>>>();
    k_red2<<<1, 32>>>((float*)d_out);
}